// round 2
// baseline (speedup 1.0000x reference)
#include <cuda_runtime.h>
#include <cuda_bf16.h>
#include <cstdint>
#include <cstddef>

#define SEQ   65536
#define HID   128
#define NG    512
#define INP   64

// 128 MB scratch for precomputed input-gate contributions (static __device__ is allowed)
static __device__ float g_xg[(size_t)SEQ * NG];

union F2U { float2 f; unsigned long long u; };

static __device__ __forceinline__ unsigned long long ld2(const float2* p) {
    F2U u; u.f = *p; return u.u;
}
static __device__ __forceinline__ unsigned long long ffma2(unsigned long long a,
                                                           unsigned long long b,
                                                           unsigned long long c) {
    unsigned long long d;
    asm("fma.rn.f32x2 %0, %1, %2, %3;" : "=l"(d) : "l"(a), "l"(b), "l"(c));
    return d;
}
static __device__ __forceinline__ unsigned long long fadd2(unsigned long long a,
                                                           unsigned long long b) {
    unsigned long long d;
    asm("add.rn.f32x2 %0, %1, %2;" : "=l"(d) : "l"(a), "l"(b));
    return d;
}
static __device__ __forceinline__ float hsum2(unsigned long long a) {
    F2U u; u.u = a; return u.f.x + u.f.y;
}
static __device__ __forceinline__ uint32_t smem_u32(const void* p) {
    uint32_t a;
    asm("{ .reg .u64 t; cvta.to.shared.u64 t, %1; cvt.u32.u64 %0, t; }"
        : "=r"(a) : "l"(p));
    return a;
}
static __device__ __forceinline__ float fsigmoid(float x) {
    return __fdividef(1.0f, 1.0f + __expf(-x));
}
static __device__ __forceinline__ float ftanh(float x) {
    // 1 - 2/(e^{2x}+1): correct saturation at +/-inf
    return 1.0f - __fdividef(2.0f, __expf(2.0f * x) + 1.0f);
}
static __device__ __forceinline__ void mbar_wait(uint32_t mb, uint32_t par) {
    asm volatile(
        "{\n\t.reg .pred P;\n"
        "W_%=:\n\t"
        "mbarrier.try_wait.parity.acquire.cluster.shared::cta.b64 P, [%0], %1;\n\t"
        "@!P bra W_%=;\n\t}"
        :: "r"(mb), "r"(par) : "memory");
}

// ---------------------------------------------------------------------------
// Phase 1: x_gates[t][r] = b_ih[r] + b_hh[r] + sum_k input[t][k]*W_ih[r][k]
// 512 blocks x 512 threads; each block does a 128-timestep tile.
// ---------------------------------------------------------------------------
__global__ void __launch_bounds__(512, 1)
gemm_xg(const float* __restrict__ x, const float* __restrict__ Wih,
        const float* __restrict__ bih, const float* __restrict__ bhh)
{
    __shared__ __align__(16) float xs[128 * INP];    // 32 KB input tile
    const int r  = threadIdx.x;                      // gate row 0..511
    const int t0 = blockIdx.x * 128;

    {   // cooperative contiguous load of input tile [128 x 64]
        const float4* src = (const float4*)(x + (size_t)t0 * INP);
        float4* dst = (float4*)xs;
        #pragma unroll
        for (int i = r; i < 128 * INP / 4; i += 512) dst[i] = src[i];
    }

    unsigned long long w[32];
    {
        const float2* wr = (const float2*)(Wih + (size_t)r * INP);
        #pragma unroll
        for (int i = 0; i < 32; i++) w[i] = ld2(wr + i);
    }
    const float bias = bih[r] + bhh[r];
    __syncthreads();

    for (int tt = 0; tt < 128; tt++) {
        const float2* xp = (const float2*)(xs + tt * INP);
        unsigned long long a0 = 0ull, a1 = 0ull, a2 = 0ull, a3 = 0ull;
        #pragma unroll
        for (int i = 0; i < 32; i += 4) {
            a0 = ffma2(w[i + 0], ld2(xp + i + 0), a0);
            a1 = ffma2(w[i + 1], ld2(xp + i + 1), a1);
            a2 = ffma2(w[i + 2], ld2(xp + i + 2), a2);
            a3 = ffma2(w[i + 3], ld2(xp + i + 3), a3);
        }
        g_xg[(size_t)(t0 + tt) * NG + r] =
            hsum2(fadd2(fadd2(a0, a1), fadd2(a2, a3))) + bias;
    }
}

// ---------------------------------------------------------------------------
// Phase 2+3: 2-CTA cluster sequential scan. CTA `rank` owns output indices
// j in [64*rank, 64*rank+64): 256 gate rows, W_hh rows fully in registers.
// Double-buffered h + per-buffer mbarrier (arrive count 64) for the 256 B
// cross-CTA h exchange each step.
// ---------------------------------------------------------------------------
__global__ void __launch_bounds__(256, 1) __cluster_dims__(2, 1, 1)
lstm_scan(const float* __restrict__ Whh,
          const float* __restrict__ Wlin,
          const float* __restrict__ blin,
          float* __restrict__ out)
{
    __shared__ __align__(16) float h_s[2][HID];
    __shared__ __align__(16) float gact[256];
    __shared__ __align__(8)  unsigned long long mbar[2];

    const int tid = threadIdx.x;
    uint32_t rank;
    asm("mov.u32 %0, %%cluster_ctarank;" : "=r"(rank));
    const uint32_t peer = rank ^ 1u;

    const int gate = tid >> 6;                  // 0:i 1:f 2:g 3:o
    const int jloc = tid & 63;
    const int grow = gate * HID + (int)rank * 64 + jloc;  // global gate row
    const int lo   = (int)rank * 32;            // local-half float2 offset
    const int ro   = lo ^ 32;                   // remote-half float2 offset

    // W_hh row in registers: w[0..31] local-k half, w[32..63] remote-k half
    unsigned long long w[64];
    {
        const float2* wr = (const float2*)(Whh + (size_t)grow * HID);
        #pragma unroll
        for (int i = 0; i < 32; i++) w[i]      = ld2(wr + lo + i);
        #pragma unroll
        for (int i = 0; i < 32; i++) w[32 + i] = ld2(wr + ro + i);
    }

    if (tid < HID) { h_s[0][tid] = 0.0f; h_s[1][tid] = 0.0f; }
    const uint32_t mb0 = smem_u32(&mbar[0]);
    const uint32_t mb1 = smem_u32(&mbar[1]);
    if (tid == 0) {
        asm volatile("mbarrier.init.shared.b64 [%0], 64;" :: "r"(mb0) : "memory");
        asm volatile("mbarrier.init.shared.b64 [%0], 64;" :: "r"(mb1) : "memory");
    }
    // peer-CTA addresses: peer's mbarriers and peer's slot for my h value
    uint32_t pmb[2];
    asm("mapa.shared::cluster.u32 %0, %1, %2;" : "=r"(pmb[0]) : "r"(mb0), "r"(peer));
    asm("mapa.shared::cluster.u32 %0, %1, %2;" : "=r"(pmb[1]) : "r"(mb1), "r"(peer));
    const int gj = (int)rank * 64 + jloc;       // my h index (tid<64 updates it)
    const uint32_t hs_a = smem_u32(&h_s[0][0]);
    uint32_t rh[2];
    asm("mapa.shared::cluster.u32 %0, %1, %2;"
        : "=r"(rh[0]) : "r"(hs_a + (uint32_t)gj * 4u), "r"(peer));
    asm("mapa.shared::cluster.u32 %0, %1, %2;"
        : "=r"(rh[1]) : "r"(hs_a + (uint32_t)(HID + gj) * 4u), "r"(peer));

    asm volatile("barrier.cluster.arrive.aligned;" ::: "memory");
    asm volatile("barrier.cluster.wait.aligned;"   ::: "memory");

    float c   = 0.0f;                            // cell state (tid<64 only)
    int par0 = 0, par1 = 0;                      // per-buffer wait parity
    float xg_next = g_xg[grow];                  // prefetch for t=0

    for (int t = 0; t < SEQ; t++) {
        const int cur = t & 1;
        const int nxt = cur ^ 1;
        const float xg = xg_next;
        if (t + 1 < SEQ) xg_next = g_xg[(size_t)(t + 1) * NG + grow];

        const float2* hp = (const float2*)h_s[cur];

        // part A: local-k half (ready via local BAR at end of prev step)
        F2U init; init.f.x = xg; init.f.y = 0.0f;
        unsigned long long a0 = init.u, a1 = 0ull, a2 = 0ull, a3 = 0ull;
        #pragma unroll
        for (int i = 0; i < 32; i += 4) {
            a0 = ffma2(w[i + 0], ld2(hp + lo + i + 0), a0);
            a1 = ffma2(w[i + 1], ld2(hp + lo + i + 1), a1);
            a2 = ffma2(w[i + 2], ld2(hp + lo + i + 2), a2);
            a3 = ffma2(w[i + 3], ld2(hp + lo + i + 3), a3);
        }

        // wait for peer's half of h (skipped at t=0: h starts at zero)
        if (t > 0) {
            if (cur == 0) { mbar_wait(mb0, par0); }   // note: all threads wait;
        }                                              // parity flipped below once
        if (t > 0 && cur == 1) { mbar_wait(mb1, par1); }

        // part B: remote-k half
        #pragma unroll
        for (int i = 0; i < 32; i += 4) {
            a0 = ffma2(w[32 + i + 0], ld2(hp + ro + i + 0), a0);
            a1 = ffma2(w[32 + i + 1], ld2(hp + ro + i + 1), a1);
            a2 = ffma2(w[32 + i + 2], ld2(hp + ro + i + 2), a2);
            a3 = ffma2(w[32 + i + 3], ld2(hp + ro + i + 3), a3);
        }
        const float s = hsum2(fadd2(fadd2(a0, a1), fadd2(a2, a3)));

        gact[tid] = (gate == 2) ? ftanh(s) : fsigmoid(s);
        if (t > 0) { if (cur == 0) par0 ^= 1; else par1 ^= 1; }
        __syncthreads();                         // gact visible; h[cur] consumed

        if (tid < 64) {
            const float iv = gact[tid];
            const float fv = gact[64  + tid];
            const float gv = gact[128 + tid];
            const float ov = gact[192 + tid];
            c = fv * c + iv * gv;
            const float hv = ov * ftanh(c);
            h_s[nxt][gj] = hv;                   // local write
            F2U hb; hb.f.x = hv;
            asm volatile("st.shared::cluster.b32 [%0], %1;"
                         :: "r"(rh[nxt]), "r"((uint32_t)__float_as_uint(hv))
                         : "memory");
            asm volatile("mbarrier.arrive.release.cluster.shared::cluster.b64 _, [%0];"
                         :: "r"(pmb[nxt]) : "memory");
            (void)hb;
        }
        __syncthreads();                         // local h[nxt] visible
    }

    // Final output on CTA 0: h_T lives in h_s[0] (local half via BAR,
    // remote half via one more mbar[0] completion from peer's last step).
    if (rank == 0) {
        mbar_wait(mb0, (uint32_t)par0);
        __syncthreads();
        if (tid < HID) gact[tid] = h_s[0][tid] * Wlin[tid];
        __syncthreads();
        if (tid == 0) {
            float acc = blin[0];
            #pragma unroll 8
            for (int j = 0; j < HID; j++) acc += gact[j];
            out[0] = fsigmoid(acc);
        }
    }

    asm volatile("barrier.cluster.arrive.aligned;" ::: "memory");
    asm volatile("barrier.cluster.wait.aligned;"   ::: "memory");
}

extern "C" void kernel_launch(void* const* d_in, const int* in_sizes, int n_in,
                              void* d_out, int out_size) {
    const float* input = (const float*)d_in[0];   // [SEQ, IN]
    const float* Wih   = (const float*)d_in[1];   // [512, 64]
    const float* Whh   = (const float*)d_in[2];   // [512, 128]
    const float* bih   = (const float*)d_in[3];   // [512]
    const float* bhh   = (const float*)d_in[4];   // [512]
    const float* Wlin  = (const float*)d_in[5];   // [1, 128]
    const float* blin  = (const float*)d_in[6];   // [1]
    float* out = (float*)d_out;

    gemm_xg<<<SEQ / 128, 512>>>(input, Wih, bih, bhh);
    lstm_scan<<<2, 256>>>(Whh, Wlin, blin, out);
}

// round 4
// speedup vs baseline: 1.7499x; 1.7499x over previous
#include <cuda_runtime.h>
#include <cuda_bf16.h>
#include <cstdint>
#include <cstddef>

#define SEQ 65536
#define HID 128
#define NG  512
#define INP 64

// Permuted x-gate scratch (+2 steps of padding for unguarded prefetch)
static __device__ float g_xg[(size_t)(SEQ + 2) * NG];

union F2U { float2 f; unsigned long long u; };

static __device__ __forceinline__ unsigned long long ld2(const float2* p) {
    F2U u; u.f = *p; return u.u;
}
static __device__ __forceinline__ unsigned long long ffma2(unsigned long long a,
                                                           unsigned long long b,
                                                           unsigned long long c) {
    unsigned long long d;
    asm("fma.rn.f32x2 %0, %1, %2, %3;" : "=l"(d) : "l"(a), "l"(b), "l"(c));
    return d;
}
static __device__ __forceinline__ unsigned long long fadd2(unsigned long long a,
                                                           unsigned long long b) {
    unsigned long long d;
    asm("add.rn.f32x2 %0, %1, %2;" : "=l"(d) : "l"(a), "l"(b));
    return d;
}
static __device__ __forceinline__ float hsum2(unsigned long long a) {
    F2U u; u.u = a; return u.f.x + u.f.y;
}
static __device__ __forceinline__ uint32_t smem_u32(const void* p) {
    uint32_t a;
    asm("{ .reg .u64 t; cvta.to.shared.u64 t, %1; cvt.u32.u64 %0, t; }"
        : "=r"(a) : "l"(p));
    return a;
}
static __device__ __forceinline__ float fex2(float x) {
    float y; asm("ex2.approx.ftz.f32 %0, %1;" : "=f"(y) : "f"(x)); return y;
}
static __device__ __forceinline__ float frcp(float x) {
    float y; asm("rcp.approx.ftz.f32 %0, %1;" : "=f"(y) : "f"(x)); return y;
}
static __device__ __forceinline__ void mbar_wait(uint32_t mb, uint32_t par) {
    asm volatile(
        "{\n\t.reg .pred P;\n"
        "W_%=:\n\t"
        "mbarrier.try_wait.parity.acquire.cta.shared::cta.b64 P, [%0], %1;\n\t"
        "@!P bra W_%=;\n\t}"
        :: "r"(mb), "r"(par) : "memory");
}
static __device__ __forceinline__ void mbar_rearm(uint32_t mb, uint32_t bytes) {
    asm volatile("mbarrier.arrive.expect_tx.shared.b64 _, [%0], %1;"
                 :: "r"(mb), "r"(bytes) : "memory");
}

#define LOG2E    1.4426950408889634f
#define TWOLOG2E 2.8853900817779268f

// ---------------------------------------------------------------------------
// Phase 1: x_gates with PERMUTED store layout:
//   row r = gate*128 + rank*64 + w*8 + jsub  ->  slot rank*256 + w*32 + gate*8 + jsub
// so each scan warp reads 128 contiguous bytes per step.
// ---------------------------------------------------------------------------
__global__ void __launch_bounds__(512, 1)
gemm_xg(const float* __restrict__ x, const float* __restrict__ Wih,
        const float* __restrict__ bih, const float* __restrict__ bhh)
{
    __shared__ __align__(16) float xs[128 * INP];
    const int r  = threadIdx.x;
    const int t0 = blockIdx.x * 128;

    {
        const float4* src = (const float4*)(x + (size_t)t0 * INP);
        float4* dst = (float4*)xs;
        #pragma unroll
        for (int i = r; i < 128 * INP / 4; i += 512) dst[i] = src[i];
    }

    unsigned long long w[32];
    {
        const float2* wr = (const float2*)(Wih + (size_t)r * INP);
        #pragma unroll
        for (int i = 0; i < 32; i++) w[i] = ld2(wr + i);
    }
    const float bias = bih[r] + bhh[r];

    const int gate = r >> 7, rk = (r >> 6) & 1, w8 = (r >> 3) & 7, js = r & 7;
    const int slot = rk * 256 + w8 * 32 + gate * 8 + js;
    __syncthreads();

    for (int tt = 0; tt < 128; tt++) {
        const float2* xp = (const float2*)(xs + tt * INP);
        unsigned long long a0 = 0ull, a1 = 0ull, a2 = 0ull, a3 = 0ull;
        #pragma unroll
        for (int i = 0; i < 32; i += 4) {
            a0 = ffma2(w[i + 0], ld2(xp + i + 0), a0);
            a1 = ffma2(w[i + 1], ld2(xp + i + 1), a1);
            a2 = ffma2(w[i + 2], ld2(xp + i + 2), a2);
            a3 = ffma2(w[i + 3], ld2(xp + i + 3), a3);
        }
        g_xg[(size_t)(t0 + tt) * NG + slot] =
            hsum2(fadd2(fadd2(a0, a1), fadd2(a2, a3))) + bias;
    }
}

// ---------------------------------------------------------------------------
// Phase 2+3: 2-CTA cluster scan, warp-local gates, st.async h exchange.
// ---------------------------------------------------------------------------
__global__ void __launch_bounds__(256, 1) __cluster_dims__(2, 1, 1)
lstm_scan(const float* __restrict__ Whh,
          const float* __restrict__ Wlin,
          const float* __restrict__ blin,
          float* __restrict__ out)
{
    __shared__ __align__(16) float h_s[2][HID];
    __shared__ __align__(8)  unsigned long long mbar[2];
    __shared__ float red[HID];

    const int tid  = threadIdx.x;
    const int w_id = tid >> 5;
    const int lane = tid & 31;
    const int gate = lane >> 3;
    const int jsub = lane & 7;

    uint32_t rank;
    asm("mov.u32 %0, %%cluster_ctarank;" : "=r"(rank));
    const uint32_t peer = rank ^ 1u;

    const int grow = gate * HID + (int)rank * 64 + w_id * 8 + jsub;
    const int lo   = (int)rank * 32;   // local-k half (float2 offset)
    const int ro   = lo ^ 32;          // remote-k half
    const int gj   = (int)rank * 64 + w_id * 8 + lane;  // valid for lane<8

    unsigned long long w[64];
    {
        const float2* wr = (const float2*)(Whh + (size_t)grow * HID);
        #pragma unroll
        for (int i = 0; i < 32; i++) w[i]      = ld2(wr + lo + i);
        #pragma unroll
        for (int i = 0; i < 32; i++) w[32 + i] = ld2(wr + ro + i);
    }

    if (tid < HID) { h_s[0][tid] = 0.0f; h_s[1][tid] = 0.0f; }
    const uint32_t mb0 = smem_u32(&mbar[0]);
    const uint32_t mb1 = smem_u32(&mbar[1]);
    if (tid == 0) {
        asm volatile("mbarrier.init.shared.b64 [%0], 1;" :: "r"(mb0) : "memory");
        asm volatile("mbarrier.init.shared.b64 [%0], 1;" :: "r"(mb1) : "memory");
        mbar_rearm(mb0, 256);   // arm phase 0: 1 arrive (done) + 256 tx bytes
        mbar_rearm(mb1, 256);
    }
    uint32_t pmb[2];
    asm("mapa.shared::cluster.u32 %0, %1, %2;" : "=r"(pmb[0]) : "r"(mb0), "r"(peer));
    asm("mapa.shared::cluster.u32 %0, %1, %2;" : "=r"(pmb[1]) : "r"(mb1), "r"(peer));
    const uint32_t hs_a = smem_u32(&h_s[0][0]);
    uint32_t rh[2];
    asm("mapa.shared::cluster.u32 %0, %1, %2;"
        : "=r"(rh[0]) : "r"(hs_a + (uint32_t)gj * 4u), "r"(peer));
    asm("mapa.shared::cluster.u32 %0, %1, %2;"
        : "=r"(rh[1]) : "r"(hs_a + (uint32_t)(HID + gj) * 4u), "r"(peer));

    __syncthreads();
    asm volatile("barrier.cluster.arrive.aligned;" ::: "memory");
    asm volatile("barrier.cluster.wait.aligned;"   ::: "memory");

    // branchless activation constants: y = aa * sigma(kc'*s) + bb
    const float kc = (gate == 2) ? -TWOLOG2E : -LOG2E;
    const float aa = (gate == 2) ? 2.0f : 1.0f;
    const float bb = (gate == 2) ? -1.0f : 0.0f;

    float c = 0.0f;
    uint32_t par0 = 0, par1 = 0;
    const float* xq = g_xg + (size_t)rank * 256 + (size_t)w_id * 32 + lane;
    float xcur[2];
    xcur[0] = xq[0];
    xcur[1] = xq[NG];

#define LSTM_STEP(T, DOWAIT)                                                   \
    {                                                                          \
        const int cur = (T) & 1, nxt = cur ^ 1;                                \
        const float xg = xcur[cur];                                            \
        xcur[cur] = xq[2 * NG];                                                \
        xq += NG;                                                              \
        const float2* hp = (const float2*)h_s[cur];                            \
        F2U ii; ii.f.x = xg; ii.f.y = 0.0f;                                    \
        unsigned long long a0 = ii.u, a1 = 0ull, a2 = 0ull, a3 = 0ull;         \
        _Pragma("unroll")                                                      \
        for (int i = 0; i < 32; i += 4) {                                      \
            a0 = ffma2(w[i + 0], ld2(hp + lo + i + 0), a0);                    \
            a1 = ffma2(w[i + 1], ld2(hp + lo + i + 1), a1);                    \
            a2 = ffma2(w[i + 2], ld2(hp + lo + i + 2), a2);                    \
            a3 = ffma2(w[i + 3], ld2(hp + lo + i + 3), a3);                    \
        }                                                                      \
        if (DOWAIT) {                                                          \
            const uint32_t mbc = cur ? mb1 : mb0;                              \
            mbar_wait(mbc, cur ? par1 : par0);                                 \
            if (cur) par1 ^= 1u; else par0 ^= 1u;                              \
            if (tid == 0) mbar_rearm(mbc, 256);                                \
        }                                                                      \
        _Pragma("unroll")                                                      \
        for (int i = 0; i < 32; i += 4) {                                      \
            a0 = ffma2(w[32 + i + 0], ld2(hp + ro + i + 0), a0);               \
            a1 = ffma2(w[32 + i + 1], ld2(hp + ro + i + 1), a1);               \
            a2 = ffma2(w[32 + i + 2], ld2(hp + ro + i + 2), a2);               \
            a3 = ffma2(w[32 + i + 3], ld2(hp + ro + i + 3), a3);               \
        }                                                                      \
        const float s = hsum2(fadd2(fadd2(a0, a1), fadd2(a2, a3)));            \
        const float y = fmaf(aa, frcp(1.0f + fex2(s * kc)), bb);               \
        const float iv = __shfl_sync(0xffffffffu, y, jsub);                    \
        const float fv = __shfl_sync(0xffffffffu, y, jsub + 8);                \
        const float gv = __shfl_sync(0xffffffffu, y, jsub + 16);               \
        const float ov = __shfl_sync(0xffffffffu, y, jsub + 24);               \
        c = fmaf(fv, c, iv * gv);                                              \
        const float th = fmaf(-2.0f, frcp(fex2(c * TWOLOG2E) + 1.0f), 1.0f);   \
        const float hv = ov * th;                                              \
        const float hn = __shfl_xor_sync(0xffffffffu, hv, 1);                  \
        if (lane < 8) {                                                        \
            h_s[nxt][gj] = hv;                                                 \
            if ((lane & 1) == 0) {                                             \
                F2U pk; pk.f.x = hv; pk.f.y = hn;                              \
                asm volatile(                                                  \
                  "st.async.shared::cluster.mbarrier::complete_tx::bytes.b64 " \
                  "[%0], %1, [%2];"                                            \
                  :: "r"(rh[nxt]), "l"(pk.u), "r"(pmb[nxt]) : "memory");       \
            }                                                                  \
        }                                                                      \
        __syncthreads();                                                       \
    }

    LSTM_STEP(0, 0)
    #pragma unroll 2
    for (int t = 1; t < SEQ; t++) {
        LSTM_STEP(t, 1)
    }

    // Drain: last writes (t=SEQ-1) targeted buffer 0 / mbar[0].
    mbar_wait(mb0, par0);
    __syncthreads();

    if (rank == 0) {
        if (tid < HID) red[tid] = h_s[0][tid] * Wlin[tid];
        __syncthreads();
        if (tid == 0) {
            float acc = blin[0];
            #pragma unroll 8
            for (int j = 0; j < HID; j++) acc += red[j];
            out[0] = frcp(1.0f + fex2(-LOG2E * acc));
        }
    } else {
        __syncthreads();
    }

    asm volatile("barrier.cluster.arrive.aligned;" ::: "memory");
    asm volatile("barrier.cluster.wait.aligned;"   ::: "memory");
}

extern "C" void kernel_launch(void* const* d_in, const int* in_sizes, int n_in,
                              void* d_out, int out_size) {
    const float* input = (const float*)d_in[0];
    const float* Wih   = (const float*)d_in[1];
    const float* Whh   = (const float*)d_in[2];
    const float* bih   = (const float*)d_in[3];
    const float* bhh   = (const float*)d_in[4];
    const float* Wlin  = (const float*)d_in[5];
    const float* blin  = (const float*)d_in[6];
    float* out = (float*)d_out;

    gemm_xg<<<SEQ / 128, 512>>>(input, Wih, bih, bhh);
    lstm_scan<<<2, 256>>>(Whh, Wlin, blin, out);
}